// round 8
// baseline (speedup 1.0000x reference)
#include <cuda_runtime.h>

// SphereConv R8: read-once + Gauss 3-mult complex accumulation + 2-deep prefetch.
// Steady-state is L2-resident (84 MB working set < 126 MB L2), so the design
// minimizes L2 traffic (x read ONCE: all 8 f per block) and L2-latency
// exposure (2-deep register prefetch) and FFMA2 count (Gauss: P1,P2,P3).
// Block 128 thr = 4b x 32mq, 4 m/thread (float4 LDG). Grid = 2mh x 256l = 512,
// 5 CTAs/SM -> single wave.

#define B_ 4
#define C_ 32
#define L_ 256
#define M_ 256
#define F_ 8
#define N_ 64

typedef unsigned long long u64;

__device__ __forceinline__ u64 pk2(float lo, float hi) {
    u64 r;
    asm("mov.b64 %0, {%1, %2};" : "=l"(r) : "f"(lo), "f"(hi));
    return r;
}
__device__ __forceinline__ void upk2(u64 v, float& lo, float& hi) {
    asm("mov.b64 {%0, %1}, %2;" : "=f"(lo), "=f"(hi) : "l"(v));
}
__device__ __forceinline__ u64 ffma2(u64 a, u64 b, u64 c) {
    u64 d;
    asm("fma.rn.f32x2 %0, %1, %2, %3;" : "=l"(d) : "l"(a), "l"(b), "l"(c));
    return d;
}
__device__ __forceinline__ u64 fadd2(u64 a, u64 b) {
    u64 d;
    asm("add.rn.f32x2 %0, %1, %2;" : "=l"(d) : "l"(a), "l"(b));
    return d;
}

__global__ void __launch_bounds__(128, 5) sphere_conv_kernel(
    const float* __restrict__ xr, const float* __restrict__ xi,
    const float* __restrict__ wr, const float* __restrict__ wi,
    float* __restrict__ out)
{
    __shared__ __align__(16) u64 swr[C_ * F_];   // {s*wr, s*wr}
    __shared__ __align__(16) u64 swi[C_ * F_];   // {s*wi, s*wi}
    __shared__ __align__(16) u64 sws[C_ * F_];   // {s*(wr+wi), dup}

    const int mh  = blockIdx.x;     // 0..1 m-half
    const int l   = blockIdx.y;     // 0..255
    const int tid = threadIdx.x;    // 0..127

    // --- weight interpolation: 256 (f,c) pairs, 2 per thread ---
    {
        float t = ((float)l / (float)(L_ - 1)) * (float)(N_ - 1);
        int lo = (int)floorf(t);
        lo = lo < 0 ? 0 : (lo > N_ - 2 ? N_ - 2 : lo);
        const float fr = t - (float)lo;
        const float s  = sqrtf(1.0f + (float)l) * (1.0f / (float)C_);
        #pragma unroll
        for (int kk = 0; kk < 2; ++kk) {
            const int idx = tid + kk * 128;       // f = idx>>5, c = idx&31
            const int f = idx >> 5, c = idx & 31;
            const int base = (f * C_ + c) * N_ + lo;
            float wrv = (wr[base] * (1.0f - fr) + wr[base + 1] * fr) * s;
            float wiv = (wi[base] * (1.0f - fr) + wi[base + 1] * fr) * s;
            swr[c * F_ + f] = pk2(wrv, wrv);
            swi[c * F_ + f] = pk2(wiv, wiv);
            const float wsv = wrv + wiv;
            sws[c * F_ + f] = pk2(wsv, wsv);
        }
    }
    __syncthreads();

    const int b  = tid >> 5;                       // 0..3
    const int mq = tid & 31;                       // 0..31
    const int m0 = (mh << 7) + (mq << 2);          // 4 m per thread

    const int base4 = (((b * C_) * L_ + l) * M_ + m0) >> 2;
    const int cstr4 = (L_ * M_) >> 2;

    const float4* __restrict__ xr4 = (const float4*)xr;
    const float4* __restrict__ xi4 = (const float4*)xi;

    // Gauss accumulators: P1 = sum wr*xr, P2 = sum wi*xi, P3 = sum (wr+wi)(xr+xi)
    u64 p1[F_][2], p2[F_][2], p3[F_][2];
    #pragma unroll
    for (int f = 0; f < F_; ++f) {
        p1[f][0] = p1[f][1] = 0ull;
        p2[f][0] = p2[f][1] = 0ull;
        p3[f][0] = p3[f][1] = 0ull;
    }

    // --- 2-deep software pipeline ---
    float4 vr0 = xr4[base4],              vi0 = xi4[base4];
    float4 vr1 = xr4[base4 + cstr4],      vi1 = xi4[base4 + cstr4];

    #pragma unroll 4
    for (int c = 0; c < C_; ++c) {
        const u64 x_r0 = pk2(vr0.x, vr0.y), x_r1 = pk2(vr0.z, vr0.w);
        const u64 x_i0 = pk2(vi0.x, vi0.y), x_i1 = pk2(vi0.z, vi0.w);
        const u64 x_s0 = fadd2(x_r0, x_i0), x_s1 = fadd2(x_r1, x_i1);

        vr0 = vr1; vi0 = vi1;                 // rotate pipeline
        if (c + 2 < C_) {
            vr1 = xr4[base4 + (c + 2) * cstr4];
            vi1 = xi4[base4 + (c + 2) * cstr4];
        }

        const ulonglong2* __restrict__ pwr = (const ulonglong2*)(swr + c * F_);
        const ulonglong2* __restrict__ pwi = (const ulonglong2*)(swi + c * F_);
        const ulonglong2* __restrict__ pws = (const ulonglong2*)(sws + c * F_);

        #pragma unroll
        for (int fp = 0; fp < F_ / 2; ++fp) {
            const ulonglong2 w_r = pwr[fp];
            const ulonglong2 w_i = pwi[fp];
            const ulonglong2 w_s = pws[fp];
            const int f0 = fp * 2;
            p1[f0][0]   = ffma2(w_r.x, x_r0, p1[f0][0]);
            p2[f0][0]   = ffma2(w_i.x, x_i0, p2[f0][0]);
            p3[f0][0]   = ffma2(w_s.x, x_s0, p3[f0][0]);
            p1[f0][1]   = ffma2(w_r.x, x_r1, p1[f0][1]);
            p2[f0][1]   = ffma2(w_i.x, x_i1, p2[f0][1]);
            p3[f0][1]   = ffma2(w_s.x, x_s1, p3[f0][1]);
            p1[f0+1][0] = ffma2(w_r.y, x_r0, p1[f0+1][0]);
            p2[f0+1][0] = ffma2(w_i.y, x_i0, p2[f0+1][0]);
            p3[f0+1][0] = ffma2(w_s.y, x_s0, p3[f0+1][0]);
            p1[f0+1][1] = ffma2(w_r.y, x_r1, p1[f0+1][1]);
            p2[f0+1][1] = ffma2(w_i.y, x_i1, p2[f0+1][1]);
            p3[f0+1][1] = ffma2(w_s.y, x_s1, p3[f0+1][1]);
        }
    }

    // --- epilogue: R = relu(P1-P2), I = P3-P1-P2, write (2, B, F, L, M) ---
    const int outHalf = B_ * F_ * L_ * M_;
    #pragma unroll
    for (int f = 0; f < F_; ++f) {
        const int oR = ((b * F_ + f) * L_ + l) * M_ + m0;
        float a0, a1, a2, a3, b0, b1, b2, b3, c0, c1, c2, c3;
        upk2(p1[f][0], a0, a1); upk2(p1[f][1], a2, a3);
        upk2(p2[f][0], b0, b1); upk2(p2[f][1], b2, b3);
        upk2(p3[f][0], c0, c1); upk2(p3[f][1], c2, c3);
        *(float4*)(out + oR) = make_float4(
            fmaxf(a0 - b0, 0.0f), fmaxf(a1 - b1, 0.0f),
            fmaxf(a2 - b2, 0.0f), fmaxf(a3 - b3, 0.0f));
        *(float4*)(out + outHalf + oR) = make_float4(
            c0 - a0 - b0, c1 - a1 - b1, c2 - a2 - b2, c3 - a3 - b3);
    }
}

extern "C" void kernel_launch(void* const* d_in, const int* in_sizes, int n_in,
                              void* d_out, int out_size) {
    const float* xr = (const float*)d_in[0];
    const float* xi = (const float*)d_in[1];
    const float* wr = (const float*)d_in[2];
    const float* wi = (const float*)d_in[3];
    float* out = (float*)d_out;
    dim3 grid(2, L_);   // (mh, l): 512 blocks, 5 CTAs/SM, single wave
    sphere_conv_kernel<<<grid, 128>>>(xr, xi, wr, wi, out);
}

// round 9
// speedup vs baseline: 2.4361x; 2.4361x over previous
#include <cuda_runtime.h>

// SphereConv R9: f-pair-packed f32x2 accumulation + Gauss 3-mult + read-once.
// Lane packing = (f_even, f_odd): weights live in smem as NATURAL pairs (no
// duplication), x scalars are duplicated with one MOV. Gauss (P1=wr*xr,
// P2=wi*xi, P3=(wr+wi)(xr+xi)) cuts FFMA2 4->3 per (f,c).
// Block 128 thr = 4b x 32mq, 2 m/thread (LDG.64), all 8 f -> x read ONCE.
// 24 u64 accums (48 regs) + 2-deep prefetch fits 85-reg cap without spill.

#define B_ 4
#define C_ 32
#define L_ 256
#define M_ 256
#define F_ 8
#define N_ 64

typedef unsigned long long u64;

__device__ __forceinline__ u64 dup1(float v) {
    u64 r;
    asm("mov.b64 %0, {%1, %1};" : "=l"(r) : "f"(v));
    return r;
}
__device__ __forceinline__ void upk2(u64 v, float& lo, float& hi) {
    asm("mov.b64 {%0, %1}, %2;" : "=f"(lo), "=f"(hi) : "l"(v));
}
__device__ __forceinline__ u64 ffma2(u64 a, u64 b, u64 c) {
    u64 d;
    asm("fma.rn.f32x2 %0, %1, %2, %3;" : "=l"(d) : "l"(a), "l"(b), "l"(c));
    return d;
}
__device__ __forceinline__ u64 fadd2(u64 a, u64 b) {
    u64 d;
    asm("add.rn.f32x2 %0, %1, %2;" : "=l"(d) : "l"(a), "l"(b));
    return d;
}

__global__ void __launch_bounds__(128, 6) sphere_conv_kernel(
    const float* __restrict__ xr, const float* __restrict__ xi,
    const float* __restrict__ wr, const float* __restrict__ wi,
    float* __restrict__ out)
{
    // natural f-pairs: swr[c*4 + p] = {s*wr[f=2p], s*wr[f=2p+1]}
    __shared__ __align__(16) u64 swr[C_ * 4];
    __shared__ __align__(16) u64 swi[C_ * 4];
    __shared__ __align__(16) u64 sws[C_ * 4];   // s*(wr+wi) pairs

    const int mg  = blockIdx.x;     // 0..3 m-group of 64
    const int l   = blockIdx.y;     // 0..255
    const int tid = threadIdx.x;    // 0..127

    // --- weight interpolation: 256 (f,c) pairs, 2 per thread, scalar writes ---
    {
        float t = ((float)l / (float)(L_ - 1)) * (float)(N_ - 1);
        int lo = (int)floorf(t);
        lo = lo < 0 ? 0 : (lo > N_ - 2 ? N_ - 2 : lo);
        const float fr = t - (float)lo;
        const float s  = sqrtf(1.0f + (float)l) * (1.0f / (float)C_);
        float* fwr = (float*)swr;
        float* fwi = (float*)swi;
        float* fws = (float*)sws;
        #pragma unroll
        for (int kk = 0; kk < 2; ++kk) {
            const int idx = tid + kk * 128;       // f = idx>>5, c = idx&31
            const int f = idx >> 5, c = idx & 31;
            const int base = (f * C_ + c) * N_ + lo;
            const float wrv = (wr[base] * (1.0f - fr) + wr[base + 1] * fr) * s;
            const float wiv = (wi[base] * (1.0f - fr) + wi[base + 1] * fr) * s;
            fwr[c * 8 + f] = wrv;                 // u64 slot c*4+(f>>1), lane f&1
            fwi[c * 8 + f] = wiv;
            fws[c * 8 + f] = wrv + wiv;
        }
    }
    __syncthreads();

    const int b  = tid >> 5;                     // 0..3
    const int mq = tid & 31;                     // 0..31
    const int m0 = (mg << 6) + (mq << 1);        // 2 m per thread, coalesced

    const int base2 = ((((b * C_) * L_ + l) * M_ + m0) >> 1);   // float2 idx c=0
    const int cstr2 = (L_ * M_) >> 1;

    const float2* __restrict__ xr2 = (const float2*)xr;
    const float2* __restrict__ xi2 = (const float2*)xi;

    // Gauss accumulators per (f-pair, m): lanes = {f_even, f_odd}
    u64 p1[4][2], p2[4][2], p3[4][2];
    #pragma unroll
    for (int q = 0; q < 4; ++q) {
        p1[q][0] = p1[q][1] = 0ull;
        p2[q][0] = p2[q][1] = 0ull;
        p3[q][0] = p3[q][1] = 0ull;
    }

    // --- 2-deep software pipeline over c ---
    float2 vr0 = xr2[base2],         vi0 = xi2[base2];
    float2 vr1 = xr2[base2 + cstr2], vi1 = xi2[base2 + cstr2];

    #pragma unroll 2
    for (int c = 0; c < C_; ++c) {
        const u64 xr_0 = dup1(vr0.x), xr_1 = dup1(vr0.y);
        const u64 xi_0 = dup1(vi0.x), xi_1 = dup1(vi0.y);
        const u64 xs_0 = fadd2(xr_0, xi_0), xs_1 = fadd2(xr_1, xi_1);

        vr0 = vr1; vi0 = vi1;
        if (c + 2 < C_) {
            vr1 = xr2[base2 + (c + 2) * cstr2];
            vi1 = xi2[base2 + (c + 2) * cstr2];
        }

        const ulonglong2* __restrict__ pwr = (const ulonglong2*)(swr + c * 4);
        const ulonglong2* __restrict__ pwi = (const ulonglong2*)(swi + c * 4);
        const ulonglong2* __restrict__ pws = (const ulonglong2*)(sws + c * 4);

        #pragma unroll
        for (int h = 0; h < 2; ++h) {            // 2 f-pairs per LDS.128
            const ulonglong2 w_r = pwr[h];
            const ulonglong2 w_i = pwi[h];
            const ulonglong2 w_s = pws[h];
            const int q0 = h * 2;
            p1[q0][0]   = ffma2(w_r.x, xr_0, p1[q0][0]);
            p2[q0][0]   = ffma2(w_i.x, xi_0, p2[q0][0]);
            p3[q0][0]   = ffma2(w_s.x, xs_0, p3[q0][0]);
            p1[q0][1]   = ffma2(w_r.x, xr_1, p1[q0][1]);
            p2[q0][1]   = ffma2(w_i.x, xi_1, p2[q0][1]);
            p3[q0][1]   = ffma2(w_s.x, xs_1, p3[q0][1]);
            p1[q0+1][0] = ffma2(w_r.y, xr_0, p1[q0+1][0]);
            p2[q0+1][0] = ffma2(w_i.y, xi_0, p2[q0+1][0]);
            p3[q0+1][0] = ffma2(w_s.y, xs_0, p3[q0+1][0]);
            p1[q0+1][1] = ffma2(w_r.y, xr_1, p1[q0+1][1]);
            p2[q0+1][1] = ffma2(w_i.y, xi_1, p2[q0+1][1]);
            p3[q0+1][1] = ffma2(w_s.y, xs_1, p3[q0+1][1]);
        }
    }

    // --- epilogue: R = relu(P1-P2), I = P3-P1-P2, write (2,B,F,L,M) ---
    const int outHalf = B_ * F_ * L_ * M_;
    #pragma unroll
    for (int q = 0; q < 4; ++q) {
        float a0e, a0o, a1e, a1o;   // P1: m0/m1 x f-even/f-odd
        float b0e, b0o, b1e, b1o;   // P2
        float c0e, c0o, c1e, c1o;   // P3
        upk2(p1[q][0], a0e, a0o); upk2(p1[q][1], a1e, a1o);
        upk2(p2[q][0], b0e, b0o); upk2(p2[q][1], b1e, b1o);
        upk2(p3[q][0], c0e, c0o); upk2(p3[q][1], c1e, c1o);

        const int fe = q * 2, fo = q * 2 + 1;
        const int oE = ((b * F_ + fe) * L_ + l) * M_ + m0;
        const int oO = ((b * F_ + fo) * L_ + l) * M_ + m0;

        *(float2*)(out + oE) = make_float2(fmaxf(a0e - b0e, 0.0f),
                                           fmaxf(a1e - b1e, 0.0f));
        *(float2*)(out + oO) = make_float2(fmaxf(a0o - b0o, 0.0f),
                                           fmaxf(a1o - b1o, 0.0f));
        *(float2*)(out + outHalf + oE) = make_float2(c0e - a0e - b0e,
                                                     c1e - a1e - b1e);
        *(float2*)(out + outHalf + oO) = make_float2(c0o - a0o - b0o,
                                                     c1o - a1o - b1o);
    }
}

extern "C" void kernel_launch(void* const* d_in, const int* in_sizes, int n_in,
                              void* d_out, int out_size) {
    const float* xr = (const float*)d_in[0];
    const float* xi = (const float*)d_in[1];
    const float* wr = (const float*)d_in[2];
    const float* wi = (const float*)d_in[3];
    float* out = (float*)d_out;
    dim3 grid(4, L_);   // (m-group, l): 1024 blocks, 6 CTAs/SM
    sphere_conv_kernel<<<grid, 128>>>(xr, xi, wr, wi, out);
}

// round 10
// speedup vs baseline: 3.3156x; 1.3610x over previous
#include <cuda_runtime.h>

// SphereConv R10: R7 skeleton (proven 21.0us) + Gauss 3-mult complex form.
// P = sum wr*xr, Q = sum wi*xi, S = sum (wr+wi)(xr+xi); R = P-Q, I = S-P-Q.
// FFMA2 per (f,c): 4 -> 3 (-25% FMA-pipe work). Everything else identical:
// 4f x 4m per thread, f-split (x via L2 for the pair), FULL c unroll,
// 1-deep compile-time prefetch, launch_bounds(128,6).

#define B_ 4
#define C_ 32
#define L_ 256
#define M_ 256
#define F_ 8
#define N_ 64
#define FH 4

typedef unsigned long long u64;

__device__ __forceinline__ u64 pk2(float lo, float hi) {
    u64 r;
    asm("mov.b64 %0, {%1, %2};" : "=l"(r) : "f"(lo), "f"(hi));
    return r;
}
__device__ __forceinline__ void upk2(u64 v, float& lo, float& hi) {
    asm("mov.b64 {%0, %1}, %2;" : "=f"(lo), "=f"(hi) : "l"(v));
}
__device__ __forceinline__ u64 ffma2(u64 a, u64 b, u64 c) {
    u64 d;
    asm("fma.rn.f32x2 %0, %1, %2, %3;" : "=l"(d) : "l"(a), "l"(b), "l"(c));
    return d;
}
__device__ __forceinline__ u64 fadd2(u64 a, u64 b) {
    u64 d;
    asm("add.rn.f32x2 %0, %1, %2;" : "=l"(d) : "l"(a), "l"(b));
    return d;
}

__global__ void __launch_bounds__(128, 6) sphere_conv_kernel(
    const float* __restrict__ xr, const float* __restrict__ xi,
    const float* __restrict__ wr, const float* __restrict__ wi,
    float* __restrict__ out)
{
    __shared__ __align__(16) u64 swr[C_ * FH];   // {s*wr, s*wr}
    __shared__ __align__(16) u64 swi[C_ * FH];   // {s*wi, s*wi}
    __shared__ __align__(16) u64 sws[C_ * FH];   // {s*(wr+wi), dup}

    const int fh  = blockIdx.x & 1;
    const int mh  = blockIdx.x >> 1;
    const int l   = blockIdx.y;
    const int tid = threadIdx.x;

    // --- weight interpolation: 128 (f_local, c) pairs == 128 threads ---
    {
        const int fl = tid >> 5;
        const int c  = tid & 31;
        const int f  = fh * FH + fl;
        float t = ((float)l / (float)(L_ - 1)) * (float)(N_ - 1);
        int lo = (int)floorf(t);
        lo = lo < 0 ? 0 : (lo > N_ - 2 ? N_ - 2 : lo);
        const float fr = t - (float)lo;
        const int base = (f * C_ + c) * N_ + lo;
        float wrv = wr[base] * (1.0f - fr) + wr[base + 1] * fr;
        float wiv = wi[base] * (1.0f - fr) + wi[base + 1] * fr;
        const float s = sqrtf(1.0f + (float)l) * (1.0f / (float)C_);
        wrv *= s; wiv *= s;
        swr[c * FH + fl] = pk2(wrv, wrv);
        swi[c * FH + fl] = pk2(wiv, wiv);
        sws[c * FH + fl] = pk2(wrv + wiv, wrv + wiv);
    }
    __syncthreads();

    const int b  = tid >> 5;
    const int mq = tid & 31;
    const int m0 = (mh << 7) + (mq << 2);     // 4 m per thread

    const int base4 = (((b * C_) * L_ + l) * M_ + m0) >> 2;
    const int cstr4 = (L_ * M_) >> 2;

    const float4* __restrict__ xr4 = (const float4*)xr;
    const float4* __restrict__ xi4 = (const float4*)xi;

    // Gauss accumulators: P = wr*xr, Q = wi*xi, S = (wr+wi)(xr+xi)
    u64 aP[FH][2], aQ[FH][2], aS[FH][2];
    #pragma unroll
    for (int f = 0; f < FH; ++f) {
        aP[f][0] = aP[f][1] = 0ull;
        aQ[f][0] = aQ[f][1] = 0ull;
        aS[f][0] = aS[f][1] = 0ull;
    }

    // --- fully unrolled, 1-deep compile-time prefetch (R7 pattern) ---
    float4 vr = xr4[base4];
    float4 vi = xi4[base4];

    #pragma unroll
    for (int c = 0; c < C_; ++c) {
        const u64 x_r0 = pk2(vr.x, vr.y), x_r1 = pk2(vr.z, vr.w);
        const u64 x_i0 = pk2(vi.x, vi.y), x_i1 = pk2(vi.z, vi.w);
        const u64 x_s0 = fadd2(x_r0, x_i0), x_s1 = fadd2(x_r1, x_i1);
        if (c + 1 < C_) {                    // compile-time resolved
            vr = xr4[base4 + (c + 1) * cstr4];
            vi = xi4[base4 + (c + 1) * cstr4];
        }

        const ulonglong2* __restrict__ pwr = (const ulonglong2*)(swr + c * FH);
        const ulonglong2* __restrict__ pwi = (const ulonglong2*)(swi + c * FH);
        const ulonglong2* __restrict__ pws = (const ulonglong2*)(sws + c * FH);

        #pragma unroll
        for (int fp = 0; fp < FH / 2; ++fp) {
            const ulonglong2 w_r = pwr[fp];
            const ulonglong2 w_i = pwi[fp];
            const ulonglong2 w_s = pws[fp];
            const int f0 = fp * 2;
            aP[f0][0]   = ffma2(w_r.x, x_r0, aP[f0][0]);
            aQ[f0][0]   = ffma2(w_i.x, x_i0, aQ[f0][0]);
            aS[f0][0]   = ffma2(w_s.x, x_s0, aS[f0][0]);
            aP[f0][1]   = ffma2(w_r.x, x_r1, aP[f0][1]);
            aQ[f0][1]   = ffma2(w_i.x, x_i1, aQ[f0][1]);
            aS[f0][1]   = ffma2(w_s.x, x_s1, aS[f0][1]);
            aP[f0+1][0] = ffma2(w_r.y, x_r0, aP[f0+1][0]);
            aQ[f0+1][0] = ffma2(w_i.y, x_i0, aQ[f0+1][0]);
            aS[f0+1][0] = ffma2(w_s.y, x_s0, aS[f0+1][0]);
            aP[f0+1][1] = ffma2(w_r.y, x_r1, aP[f0+1][1]);
            aQ[f0+1][1] = ffma2(w_i.y, x_i1, aQ[f0+1][1]);
            aS[f0+1][1] = ffma2(w_s.y, x_s1, aS[f0+1][1]);
        }
    }

    // --- epilogue: R = relu(P-Q), I = S-P-Q, write (2, B, F, L, M) ---
    const int outHalf = B_ * F_ * L_ * M_;
    #pragma unroll
    for (int fl = 0; fl < FH; ++fl) {
        const int f  = fh * FH + fl;
        const int oR = ((b * F_ + f) * L_ + l) * M_ + m0;
        float p0, p1, p2, p3, q0, q1, q2, q3, s0, s1, s2, s3;
        upk2(aP[fl][0], p0, p1); upk2(aP[fl][1], p2, p3);
        upk2(aQ[fl][0], q0, q1); upk2(aQ[fl][1], q2, q3);
        upk2(aS[fl][0], s0, s1); upk2(aS[fl][1], s2, s3);
        *(float4*)(out + oR) = make_float4(
            fmaxf(p0 - q0, 0.0f), fmaxf(p1 - q1, 0.0f),
            fmaxf(p2 - q2, 0.0f), fmaxf(p3 - q3, 0.0f));
        *(float4*)(out + outHalf + oR) = make_float4(
            s0 - p0 - q0, s1 - p1 - q1, s2 - p2 - q2, s3 - p3 - q3);
    }
}

extern "C" void kernel_launch(void* const* d_in, const int* in_sizes, int n_in,
                              void* d_out, int out_size) {
    const float* xr = (const float*)d_in[0];
    const float* xi = (const float*)d_in[1];
    const float* wr = (const float*)d_in[2];
    const float* wi = (const float*)d_in[3];
    float* out = (float*)d_out;
    dim3 grid(4, L_);   // (fh|mh, l) — fh fastest: f-half pairs co-resident
    sphere_conv_kernel<<<grid, 128>>>(xr, xi, wr, wi, out);
}

// round 11
// speedup vs baseline: 4.2621x; 1.2855x over previous
#include <cuda_runtime.h>

// SphereConv R11: R7 skeleton + 3-deep register prefetch ring.
// Diagnosis: all ~21us configs have per-warp MLP ~= 2 (only the current pair
// of LDG.128 in flight) -> latency-limited ~4 TB/s. Ring of 3 (vr,vi) slots
// keeps 6 LDG.128 in flight per warp (compile-time indices, no branches).
// Everything else = R7: 4f x 4m/thread, f-split, split accums (Rp,Rm,I),
// full c unroll. launch_bounds(128,5) -> 102-reg budget (need ~96, no spill).

#define B_ 4
#define C_ 32
#define L_ 256
#define M_ 256
#define F_ 8
#define N_ 64
#define FH 4
#define DEPTH 3

typedef unsigned long long u64;

__device__ __forceinline__ u64 pk2(float lo, float hi) {
    u64 r;
    asm("mov.b64 %0, {%1, %2};" : "=l"(r) : "f"(lo), "f"(hi));
    return r;
}
__device__ __forceinline__ void upk2(u64 v, float& lo, float& hi) {
    asm("mov.b64 {%0, %1}, %2;" : "=f"(lo), "=f"(hi) : "l"(v));
}
__device__ __forceinline__ u64 ffma2(u64 a, u64 b, u64 c) {
    u64 d;
    asm("fma.rn.f32x2 %0, %1, %2, %3;" : "=l"(d) : "l"(a), "l"(b), "l"(c));
    return d;
}

__global__ void __launch_bounds__(128, 5) sphere_conv_kernel(
    const float* __restrict__ xr, const float* __restrict__ xi,
    const float* __restrict__ wr, const float* __restrict__ wi,
    float* __restrict__ out)
{
    __shared__ __align__(16) u64 swr[C_ * FH];   // {s*wr, s*wr}
    __shared__ __align__(16) u64 swi[C_ * FH];   // {s*wi, s*wi}

    const int fh  = blockIdx.x & 1;
    const int mh  = blockIdx.x >> 1;
    const int l   = blockIdx.y;
    const int tid = threadIdx.x;

    // --- weight interpolation: 128 (f_local, c) pairs == 128 threads ---
    {
        const int fl = tid >> 5;
        const int c  = tid & 31;
        const int f  = fh * FH + fl;
        float t = ((float)l / (float)(L_ - 1)) * (float)(N_ - 1);
        int lo = (int)floorf(t);
        lo = lo < 0 ? 0 : (lo > N_ - 2 ? N_ - 2 : lo);
        const float fr = t - (float)lo;
        const int base = (f * C_ + c) * N_ + lo;
        float wrv = wr[base] * (1.0f - fr) + wr[base + 1] * fr;
        float wiv = wi[base] * (1.0f - fr) + wi[base + 1] * fr;
        const float s = sqrtf(1.0f + (float)l) * (1.0f / (float)C_);
        wrv *= s; wiv *= s;
        swr[c * FH + fl] = pk2(wrv, wrv);
        swi[c * FH + fl] = pk2(wiv, wiv);
    }
    __syncthreads();

    const int b  = tid >> 5;
    const int mq = tid & 31;
    const int m0 = (mh << 7) + (mq << 2);     // 4 m per thread

    const int base4 = (((b * C_) * L_ + l) * M_ + m0) >> 2;
    const int cstr4 = (L_ * M_) >> 2;

    const float4* __restrict__ xr4 = (const float4*)xr;
    const float4* __restrict__ xi4 = (const float4*)xi;

    // split accumulators: Rp = wr*xr, Rm = wi*xi, I = wr*xi + wi*xr
    u64 aRp[FH][2], aRm[FH][2], aI[FH][2];
    #pragma unroll
    for (int f = 0; f < FH; ++f) {
        aRp[f][0] = aRp[f][1] = 0ull;
        aRm[f][0] = aRm[f][1] = 0ull;
        aI [f][0] = aI [f][1] = 0ull;
    }

    // --- 3-deep prefetch ring: 6 LDG.128 in flight per warp ---
    float4 vr[DEPTH], vi[DEPTH];
    #pragma unroll
    for (int s = 0; s < DEPTH; ++s) {
        vr[s] = xr4[base4 + s * cstr4];
        vi[s] = xi4[base4 + s * cstr4];
    }

    #pragma unroll
    for (int c = 0; c < C_; ++c) {
        const int slot = c % DEPTH;           // compile-time under full unroll
        const u64 x_r0 = pk2(vr[slot].x, vr[slot].y);
        const u64 x_r1 = pk2(vr[slot].z, vr[slot].w);
        const u64 x_i0 = pk2(vi[slot].x, vi[slot].y);
        const u64 x_i1 = pk2(vi[slot].z, vi[slot].w);
        if (c + DEPTH < C_) {                 // compile-time resolved
            vr[slot] = xr4[base4 + (c + DEPTH) * cstr4];
            vi[slot] = xi4[base4 + (c + DEPTH) * cstr4];
        }

        const ulonglong2* __restrict__ pwr = (const ulonglong2*)(swr + c * FH);
        const ulonglong2* __restrict__ pwi = (const ulonglong2*)(swi + c * FH);

        #pragma unroll
        for (int fp = 0; fp < FH / 2; ++fp) {
            const ulonglong2 w_r = pwr[fp];
            const ulonglong2 w_i = pwi[fp];
            const int f0 = fp * 2;
            aRp[f0][0]   = ffma2(w_r.x, x_r0, aRp[f0][0]);
            aRm[f0][0]   = ffma2(w_i.x, x_i0, aRm[f0][0]);
            aI [f0][0]   = ffma2(w_r.x, x_i0, aI [f0][0]);
            aI [f0][0]   = ffma2(w_i.x, x_r0, aI [f0][0]);
            aRp[f0][1]   = ffma2(w_r.x, x_r1, aRp[f0][1]);
            aRm[f0][1]   = ffma2(w_i.x, x_i1, aRm[f0][1]);
            aI [f0][1]   = ffma2(w_r.x, x_i1, aI [f0][1]);
            aI [f0][1]   = ffma2(w_i.x, x_r1, aI [f0][1]);
            aRp[f0+1][0] = ffma2(w_r.y, x_r0, aRp[f0+1][0]);
            aRm[f0+1][0] = ffma2(w_i.y, x_i0, aRm[f0+1][0]);
            aI [f0+1][0] = ffma2(w_r.y, x_i0, aI [f0+1][0]);
            aI [f0+1][0] = ffma2(w_i.y, x_r0, aI [f0+1][0]);
            aRp[f0+1][1] = ffma2(w_r.y, x_r1, aRp[f0+1][1]);
            aRm[f0+1][1] = ffma2(w_i.y, x_i1, aRm[f0+1][1]);
            aI [f0+1][1] = ffma2(w_r.y, x_i1, aI [f0+1][1]);
            aI [f0+1][1] = ffma2(w_i.y, x_r1, aI [f0+1][1]);
        }
    }

    // --- epilogue: r = relu(p - m), write (2, B, F, L, M) ---
    const int outHalf = B_ * F_ * L_ * M_;
    #pragma unroll
    for (int fl = 0; fl < FH; ++fl) {
        const int f  = fh * FH + fl;
        const int oR = ((b * F_ + f) * L_ + l) * M_ + m0;
        float p0, p1, p2, p3, q0, q1, q2, q3, i0, i1, i2, i3;
        upk2(aRp[fl][0], p0, p1); upk2(aRp[fl][1], p2, p3);
        upk2(aRm[fl][0], q0, q1); upk2(aRm[fl][1], q2, q3);
        upk2(aI [fl][0], i0, i1); upk2(aI [fl][1], i2, i3);
        *(float4*)(out + oR) = make_float4(
            fmaxf(p0 - q0, 0.0f), fmaxf(p1 - q1, 0.0f),
            fmaxf(p2 - q2, 0.0f), fmaxf(p3 - q3, 0.0f));
        *(float4*)(out + outHalf + oR) = make_float4(i0, i1, i2, i3);
    }
}

extern "C" void kernel_launch(void* const* d_in, const int* in_sizes, int n_in,
                              void* d_out, int out_size) {
    const float* xr = (const float*)d_in[0];
    const float* xi = (const float*)d_in[1];
    const float* wr = (const float*)d_in[2];
    const float* wi = (const float*)d_in[3];
    float* out = (float*)d_out;
    dim3 grid(4, L_);   // (fh|mh, l) — fh fastest: f-half pairs co-resident
    sphere_conv_kernel<<<grid, 128>>>(xr, xi, wr, wi, out);
}